// round 4
// baseline (speedup 1.0000x reference)
#include <cuda_runtime.h>
#include <cuda_bf16.h>

#define NUM_NODES 2
#define D_W       13          // n*n + 4n + 1 = 13
#define K_COMP    8192
#define N_SAMP    8192
#define B_X       2048
#define ALPHA_C   1.0f
#define BETA_C    5.0f
#define KLBETA_C  1.0f

#define LOG_2PI_F 1.8378770664093453f
#define L2E_F     1.4426950408889634f   // log2(e)
#define LN2_F     0.6931471805599453f

// ---------------- scratch (device globals; no allocation allowed) ----------------
// emp row (16): [e0*s .. e12*s, s, c1*L2E, 1.0]   with s = (1/var)*log2(e)
// w   row (16): [w0 .. w12, -0.5*ww, 1.0, -C*L2E]
// dot16(E, W) = full log2-domain anchored logsumexp argument.
__device__ float  g_emp_pad[K_COMP * 16];
__device__ float  g_w_pad  [N_SAMP * 16];
__device__ float  g_base   [N_SAMP];       // C_s - prior_s
__device__ float2 g_kinfo  [K_COMP];       // {std, log(var)}
__device__ float  g_accum  [2];            // [0] sum d^2, [1] sum (C + ln S - prior)

// ---------------- tiny PTX helpers ----------------
__device__ __forceinline__ unsigned long long pk2(float lo, float hi) {
    unsigned long long r;
    asm("mov.b64 %0, {%1,%2};" : "=l"(r) : "f"(lo), "f"(hi));
    return r;
}
__device__ __forceinline__ void upk2(unsigned long long v, float& lo, float& hi) {
    asm("mov.b64 {%0,%1}, %2;" : "=f"(lo), "=f"(hi) : "l"(v));
}
__device__ __forceinline__ unsigned long long ffma2(unsigned long long a,
                                                    unsigned long long b,
                                                    unsigned long long c) {
    unsigned long long d;
    asm("fma.rn.f32x2 %0, %1, %2, %3;" : "=l"(d) : "l"(a), "l"(b), "l"(c));
    return d;
}
__device__ __forceinline__ float ex2f(float x) {
    float r; asm("ex2.approx.f32 %0, %1;" : "=f"(r) : "f"(x)); return r;
}
__device__ __forceinline__ float tanh_fast(float x) {
    float r; asm("tanh.approx.f32 %0, %1;" : "=f"(r) : "f"(x)); return r;
}

// ---------------- kernel A: per-component prep ----------------
__global__ void kprep(const float* __restrict__ emp, const float* __restrict__ rhos) {
    int k = blockIdx.x * blockDim.x + threadIdx.x;
    if (blockIdx.x == 0 && threadIdx.x == 0) { g_accum[0] = 0.f; g_accum[1] = 0.f; }
    if (k >= K_COMP) return;

    float rho = rhos[k];
    float std = (rho > 0.f) ? (rho + log1pf(__expf(-rho))) : log1pf(__expf(rho));
    float var = std * std;
    float iv  = 1.0f / var;
    float lv  = logf(var);
    float s   = iv * L2E_F;

    const float* er = emp + k * D_W;
    float out[16];
    float ee = 0.f;
#pragma unroll
    for (int d = 0; d < D_W; d++) {
        float v = er[d];
        ee = fmaf(v, v, ee);
        out[d] = v * s;
    }
    float c1 = -0.5f * ((float)D_W * LOG_2PI_F + (float)D_W * lv + ee * iv);
    out[13] = s;
    out[14] = c1 * L2E_F;
    out[15] = 1.0f;

    float4* dst = (float4*)(g_emp_pad + k * 16);
#pragma unroll
    for (int q = 0; q < 4; q++)
        dst[q] = make_float4(out[4*q], out[4*q+1], out[4*q+2], out[4*q+3]);
    g_kinfo[k] = make_float2(std, lv);
}

// ---------------- kernel B: per-sample prep (build w, anchors) ----------------
__global__ void ksprep(const float* __restrict__ emp, const float* __restrict__ eps,
                       const int* __restrict__ idx) {
    int s = blockIdx.x * blockDim.x + threadIdx.x;
    if (s >= N_SAMP) return;
    int j = idx[s];
    float2 ki = g_kinfo[j];
    float std = ki.x, lv = ki.y;

    const float* er = emp + j * D_W;      // raw emp (emp_pad is scaled)
    const float* ep = eps + s * D_W;
    float out[16];
    float ww = 0.f, eq = 0.f;
#pragma unroll
    for (int d = 0; d < D_W; d++) {
        float ev = er[d], e = ep[d];
        float wv = fmaf(e, std, ev);
        out[d] = wv;
        ww = fmaf(wv, wv, ww);
        eq = fmaf(e, e, eq);
    }

    // anchor: lp at self component = -0.5*(d*log2pi + d*log var_j + ||eps||^2)
    float C = -0.5f * ((float)D_W * LOG_2PI_F + (float)D_W * lv + eq);
    float prior = fmaf(-0.5f * ALPHA_C, ww, 0.5f * (float)D_W * (logf(ALPHA_C) - LOG_2PI_F));

    out[13] = -0.5f * ww;
    out[14] = 1.0f;
    out[15] = -C * L2E_F;

    float4* dst = (float4*)(g_w_pad + s * 16);
#pragma unroll
    for (int q = 0; q < 4; q++)
        dst[q] = make_float4(out[4*q], out[4*q+1], out[4*q+2], out[4*q+3]);
    g_base[s] = C - prior;
}

// ---------------- kernel C: tiny-MLP regression, accumulate sum of (pred-y)^2 ----------------
__global__ void __launch_bounds__(256) kreg(const float* __restrict__ x,
                                            const float* __restrict__ y) {
    __shared__ float2 xy[B_X];
    int tid = threadIdx.x;
    for (int i = tid; i < B_X; i += 256) xy[i] = make_float2(x[i], y[i]);
    __syncthreads();

    int s    = blockIdx.x * 8 + (tid >> 5);   // one warp per sample
    int lane = tid & 31;
    const float* w = g_w_pad + s * 16;
    float w10 = w[0],  w11 = w[1],  b10 = w[2], b11 = w[3];
    float w200 = w[4], w201 = w[5], w210 = w[6], w211 = w[7];
    float b20 = w[8],  b21 = w[9],  w30 = w[10], w31 = w[11], b3 = w[12];

    float acc = 0.f;
#pragma unroll 4
    for (int b = lane; b < B_X; b += 32) {
        float2 p = xy[b];
        float h0 = tanh_fast(fmaf(w10, p.x, b10));
        float h1 = tanh_fast(fmaf(w11, p.x, b11));
        float g0 = tanh_fast(fmaf(w200, h0, fmaf(w201, h1, b20)));
        float g1 = tanh_fast(fmaf(w210, h0, fmaf(w211, h1, b21)));
        float pr = fmaf(w30, g0, fmaf(w31, g1, b3));
        float d  = pr - p.y;
        acc = fmaf(d, d, acc);
    }
#pragma unroll
    for (int o = 16; o > 0; o >>= 1) acc += __shfl_xor_sync(0xffffffffu, acc, o);
    if (lane == 0) atomicAdd(&g_accum[0], acc);
}

// ---------------- kernel D: KDE logsumexp (the big one) ----------------
// block = 256 threads = 8 warps; each warp owns 4 samples, lanes stride k by 32.
// Per (s,k) pair: 8 FFMA2 + 1 FADD + 1 EX2 + 1 FADD. The 16-lane dot yields
// the complete anchored log2-domain argument (affine terms ride the pad lanes).
__global__ void __launch_bounds__(256, 1) kkde() {
    int tid  = threadIdx.x;
    int lane = tid & 31;
    int wid  = tid >> 5;
    int s0   = blockIdx.x * 32 + wid * 4;

    unsigned long long wp[4][8];
#pragma unroll
    for (int i = 0; i < 4; i++) {
        const float4* wr = (const float4*)(g_w_pad + (s0 + i) * 16);
        float4 a = wr[0], b = wr[1], c = wr[2], d = wr[3];
        wp[i][0] = pk2(a.x, a.y); wp[i][1] = pk2(a.z, a.w);
        wp[i][2] = pk2(b.x, b.y); wp[i][3] = pk2(b.z, b.w);
        wp[i][4] = pk2(c.x, c.y); wp[i][5] = pk2(c.z, c.w);
        wp[i][6] = pk2(d.x, d.y); wp[i][7] = pk2(d.z, d.w);  // (w12,wwh),(1,mC2)
    }

    float acc[4] = {0.f, 0.f, 0.f, 0.f};

#pragma unroll 2
    for (int k = lane; k < K_COMP; k += 32) {
        const float4* er = (const float4*)(g_emp_pad + k * 16);
        float4 e0 = er[0], e1 = er[1], e2 = er[2], e3 = er[3];
        unsigned long long ep[8];
        ep[0] = pk2(e0.x, e0.y); ep[1] = pk2(e0.z, e0.w);
        ep[2] = pk2(e1.x, e1.y); ep[3] = pk2(e1.z, e1.w);
        ep[4] = pk2(e2.x, e2.y); ep[5] = pk2(e2.z, e2.w);
        ep[6] = pk2(e3.x, e3.y); ep[7] = pk2(e3.z, e3.w);  // (e12s,s),(c12,1)

#pragma unroll
        for (int i = 0; i < 4; i++) {
            unsigned long long a2 = 0ull;
#pragma unroll
            for (int p = 0; p < 8; p++) a2 = ffma2(ep[p], wp[i][p], a2);
            float lo, hi; upk2(a2, lo, hi);
            acc[i] += ex2f(lo + hi);                   // arg = lo + hi, complete
        }
    }

#pragma unroll
    for (int i = 0; i < 4; i++)
#pragma unroll
        for (int o = 16; o > 0; o >>= 1)
            acc[i] += __shfl_xor_sync(0xffffffffu, acc[i], o);

    if (lane == 0) {
        float t = 0.f;
#pragma unroll
        for (int i = 0; i < 4; i++)
            t += g_base[s0 + i] + LN2_F * log2f(acc[i]);
        atomicAdd(&g_accum[1], t);
    }
}

// ---------------- kernel E: final combine ----------------
__global__ void kfin(float* __restrict__ out) {
    float sumd2 = g_accum[0];
    float klsum = g_accum[1];
    float data_lp = -0.5f * BETA_C * sumd2 / (float)N_SAMP
                  + (float)B_X * 0.5f * (logf(BETA_C) - LOG_2PI_F);
    float kl = klsum / (float)N_SAMP - logf((float)K_COMP);
    out[0] = data_lp - KLBETA_C * kl;
}

// ---------------- launch ----------------
extern "C" void kernel_launch(void* const* d_in, const int* in_sizes, int n_in,
                              void* d_out, int out_size) {
    const float* emp  = (const float*)d_in[0];
    const float* rhos = (const float*)d_in[1];
    const float* x    = (const float*)d_in[2];
    const float* y    = (const float*)d_in[3];
    const float* eps  = (const float*)d_in[4];
    const int*   idx  = (const int*)  d_in[5];

    kprep <<<(K_COMP + 255) / 256, 256>>>(emp, rhos);
    ksprep<<<(N_SAMP + 255) / 256, 256>>>(emp, eps, idx);
    kreg  <<<N_SAMP / 8, 256>>>(x, y);
    kkde  <<<N_SAMP / 32, 256>>>();
    kfin  <<<1, 1>>>((float*)d_out);
}

// round 6
// speedup vs baseline: 1.6873x; 1.6873x over previous
#include <cuda_runtime.h>
#include <cuda_bf16.h>

#define NUM_NODES 2
#define D_W       13          // n*n + 4n + 1 = 13
#define K_COMP    8192
#define N_SAMP    8192
#define B_X       2048
#define ALPHA_C   1.0f
#define BETA_C    5.0f
#define KLBETA_C  1.0f

#define LOG_2PI_F 1.8378770664093453f
#define L2E_F     1.4426950408889634f   // log2(e)
#define LN2_F     0.6931471805599453f

// ---------------- scratch (device globals; no allocation allowed) ----------------
// emp row (16 lanes, SoA float4 planes for coalesced lane-per-k loads):
//   plane0[k]={e0s,e1s,e2s,e3s} plane1[k]={e4s..} plane2[k]={e8s..}
//   plane3[k]={e12s, s, c1*L2E, 1.0}           with s = (1/var)*log2(e)
// w row (16): [w0 .. w12, -0.5*ww, 1.0, -C*L2E]
// dot16(E_k, W_s) = complete log2-domain anchored logsumexp argument.
__device__ float4 g_empP[4][K_COMP];
__device__ float  g_w_pad[N_SAMP * 16];
__device__ float  g_base [N_SAMP];         // C_s - prior_s
__device__ float2 g_kinfo[K_COMP];         // {std, log(var)}
__device__ float  g_accum[2];              // [0] sum d^2, [1] sum (C + ln S - prior)

// ---------------- tiny PTX helpers ----------------
__device__ __forceinline__ unsigned long long pk2(float lo, float hi) {
    unsigned long long r;
    asm("mov.b64 %0, {%1,%2};" : "=l"(r) : "f"(lo), "f"(hi));
    return r;
}
__device__ __forceinline__ void upk2(unsigned long long v, float& lo, float& hi) {
    asm("mov.b64 {%0,%1}, %2;" : "=f"(lo), "=f"(hi) : "l"(v));
}
__device__ __forceinline__ unsigned long long ffma2(unsigned long long a,
                                                    unsigned long long b,
                                                    unsigned long long c) {
    unsigned long long d;
    asm("fma.rn.f32x2 %0, %1, %2, %3;" : "=l"(d) : "l"(a), "l"(b), "l"(c));
    return d;
}
__device__ __forceinline__ float ex2f(float x) {
    float r; asm("ex2.approx.f32 %0, %1;" : "=f"(r) : "f"(x)); return r;
}
__device__ __forceinline__ float tanh_fast(float x) {
    float r; asm("tanh.approx.f32 %0, %1;" : "=f"(r) : "f"(x)); return r;
}

// ---------------- kernel A: per-component prep ----------------
__global__ void kprep(const float* __restrict__ emp, const float* __restrict__ rhos) {
    int k = blockIdx.x * blockDim.x + threadIdx.x;
    if (blockIdx.x == 0 && threadIdx.x == 0) { g_accum[0] = 0.f; g_accum[1] = 0.f; }
    if (k >= K_COMP) return;

    float rho = rhos[k];
    float std = (rho > 0.f) ? (rho + log1pf(__expf(-rho))) : log1pf(__expf(rho));
    float var = std * std;
    float iv  = 1.0f / var;
    float lv  = logf(var);
    float s   = iv * L2E_F;

    const float* er = emp + k * D_W;
    float out[16];
    float ee = 0.f;
#pragma unroll
    for (int d = 0; d < D_W; d++) {
        float v = er[d];
        ee = fmaf(v, v, ee);
        out[d] = v * s;
    }
    float c1 = -0.5f * ((float)D_W * LOG_2PI_F + (float)D_W * lv + ee * iv);
    out[13] = s;
    out[14] = c1 * L2E_F;
    out[15] = 1.0f;

#pragma unroll
    for (int q = 0; q < 4; q++)
        g_empP[q][k] = make_float4(out[4*q], out[4*q+1], out[4*q+2], out[4*q+3]);
    g_kinfo[k] = make_float2(std, lv);
}

// ---------------- kernel B: per-sample prep (build w, anchors) ----------------
__global__ void ksprep(const float* __restrict__ emp, const float* __restrict__ eps,
                       const int* __restrict__ idx) {
    int s = blockIdx.x * blockDim.x + threadIdx.x;
    if (s >= N_SAMP) return;
    int j = idx[s];
    float2 ki = g_kinfo[j];
    float std = ki.x, lv = ki.y;

    const float* er = emp + j * D_W;      // raw emp (planes are pre-scaled)
    const float* ep = eps + s * D_W;
    float out[16];
    float ww = 0.f, eq = 0.f;
#pragma unroll
    for (int d = 0; d < D_W; d++) {
        float ev = er[d], e = ep[d];
        float wv = fmaf(e, std, ev);
        out[d] = wv;
        ww = fmaf(wv, wv, ww);
        eq = fmaf(e, e, eq);
    }

    // anchor: lp at self component = -0.5*(d*log2pi + d*log var_j + ||eps||^2)
    float C = -0.5f * ((float)D_W * LOG_2PI_F + (float)D_W * lv + eq);
    float prior = fmaf(-0.5f * ALPHA_C, ww, 0.5f * (float)D_W * (logf(ALPHA_C) - LOG_2PI_F));

    out[13] = -0.5f * ww;
    out[14] = 1.0f;
    out[15] = -C * L2E_F;

    float4* dst = (float4*)(g_w_pad + s * 16);
#pragma unroll
    for (int q = 0; q < 4; q++)
        dst[q] = make_float4(out[4*q], out[4*q+1], out[4*q+2], out[4*q+3]);
    g_base[s] = C - prior;
}

// ---------------- kernel C: tiny-MLP regression, accumulate sum of (pred-y)^2 ----------------
__global__ void __launch_bounds__(256) kreg(const float* __restrict__ x,
                                            const float* __restrict__ y) {
    __shared__ float2 xy[B_X];
    int tid = threadIdx.x;
    for (int i = tid; i < B_X; i += 256) xy[i] = make_float2(x[i], y[i]);
    __syncthreads();

    int s    = blockIdx.x * 8 + (tid >> 5);   // one warp per sample
    int lane = tid & 31;
    const float* w = g_w_pad + s * 16;
    float w10 = w[0],  w11 = w[1],  b10 = w[2], b11 = w[3];
    float w200 = w[4], w201 = w[5], w210 = w[6], w211 = w[7];
    float b20 = w[8],  b21 = w[9],  w30 = w[10], w31 = w[11], b3 = w[12];

    float acc = 0.f;
#pragma unroll 4
    for (int b = lane; b < B_X; b += 32) {
        float2 p = xy[b];
        float h0 = tanh_fast(fmaf(w10, p.x, b10));
        float h1 = tanh_fast(fmaf(w11, p.x, b11));
        float g0 = tanh_fast(fmaf(w200, h0, fmaf(w201, h1, b20)));
        float g1 = tanh_fast(fmaf(w210, h0, fmaf(w211, h1, b21)));
        float pr = fmaf(w30, g0, fmaf(w31, g1, b3));
        float d  = pr - p.y;
        acc = fmaf(d, d, acc);
    }
#pragma unroll
    for (int o = 16; o > 0; o >>= 1) acc += __shfl_xor_sync(0xffffffffu, acc, o);
    if (lane == 0) atomicAdd(&g_accum[0], acc);
}

// ---------------- kernel D: KDE logsumexp (the big one) ----------------
// block = 256 threads = 8 warps; each warp owns 4 samples, lanes stride k by 32.
// emp loads hit the SoA float4 planes: lane-consecutive k -> 16B lane stride ->
// each LDG.128 covers exactly 4 cache lines (coalescing floor).
__global__ void __launch_bounds__(256, 1) kkde() {
    int tid  = threadIdx.x;
    int lane = tid & 31;
    int wid  = tid >> 5;
    int s0   = blockIdx.x * 32 + wid * 4;

    unsigned long long wp[4][8];
#pragma unroll
    for (int i = 0; i < 4; i++) {
        const float4* wr = (const float4*)(g_w_pad + (s0 + i) * 16);
        float4 a = wr[0], b = wr[1], c = wr[2], d = wr[3];
        wp[i][0] = pk2(a.x, a.y); wp[i][1] = pk2(a.z, a.w);
        wp[i][2] = pk2(b.x, b.y); wp[i][3] = pk2(b.z, b.w);
        wp[i][4] = pk2(c.x, c.y); wp[i][5] = pk2(c.z, c.w);
        wp[i][6] = pk2(d.x, d.y); wp[i][7] = pk2(d.z, d.w);  // (w12,wwh),(1,mC2)
    }

    float acc[4] = {0.f, 0.f, 0.f, 0.f};

#pragma unroll 2
    for (int k = lane; k < K_COMP; k += 32) {
        float4 e0 = g_empP[0][k];
        float4 e1 = g_empP[1][k];
        float4 e2 = g_empP[2][k];
        float4 e3 = g_empP[3][k];
        unsigned long long ep[8];
        ep[0] = pk2(e0.x, e0.y); ep[1] = pk2(e0.z, e0.w);
        ep[2] = pk2(e1.x, e1.y); ep[3] = pk2(e1.z, e1.w);
        ep[4] = pk2(e2.x, e2.y); ep[5] = pk2(e2.z, e2.w);
        ep[6] = pk2(e3.x, e3.y); ep[7] = pk2(e3.z, e3.w);  // (e12s,s),(c12,1)

#pragma unroll
        for (int i = 0; i < 4; i++) {
            unsigned long long a2 = 0ull;
#pragma unroll
            for (int p = 0; p < 8; p++) a2 = ffma2(ep[p], wp[i][p], a2);
            float lo, hi; upk2(a2, lo, hi);
            acc[i] += ex2f(lo + hi);                   // arg = lo + hi, complete
        }
    }

#pragma unroll
    for (int i = 0; i < 4; i++)
#pragma unroll
        for (int o = 16; o > 0; o >>= 1)
            acc[i] += __shfl_xor_sync(0xffffffffu, acc[i], o);

    if (lane == 0) {
        float t = 0.f;
#pragma unroll
        for (int i = 0; i < 4; i++)
            t += g_base[s0 + i] + LN2_F * log2f(acc[i]);
        atomicAdd(&g_accum[1], t);
    }
}

// ---------------- kernel E: final combine ----------------
__global__ void kfin(float* __restrict__ out) {
    float sumd2 = g_accum[0];
    float klsum = g_accum[1];
    float data_lp = -0.5f * BETA_C * sumd2 / (float)N_SAMP
                  + (float)B_X * 0.5f * (logf(BETA_C) - LOG_2PI_F);
    float kl = klsum / (float)N_SAMP - logf((float)K_COMP);
    out[0] = data_lp - KLBETA_C * kl;
}

// ---------------- launch ----------------
extern "C" void kernel_launch(void* const* d_in, const int* in_sizes, int n_in,
                              void* d_out, int out_size) {
    const float* emp  = (const float*)d_in[0];
    const float* rhos = (const float*)d_in[1];
    const float* x    = (const float*)d_in[2];
    const float* y    = (const float*)d_in[3];
    const float* eps  = (const float*)d_in[4];
    const int*   idx  = (const int*)  d_in[5];

    kprep <<<(K_COMP + 255) / 256, 256>>>(emp, rhos);
    ksprep<<<(N_SAMP + 255) / 256, 256>>>(emp, eps, idx);
    kreg  <<<N_SAMP / 8, 256>>>(x, y);
    kkde  <<<N_SAMP / 32, 256>>>();
    kfin  <<<1, 1>>>((float*)d_out);
}